// round 4
// baseline (speedup 1.0000x reference)
#include <cuda_runtime.h>
#include <cstdint>

#define NB    256
#define NNEG  1024
#define DD    256
#define DD2   512
#define BM    128
#define BK    32
#define STAGES 3
#define AS_FLOATS (BM * 36)                    // 4608 floats (A stage)
#define BS_FLOATS (DD * 36)                    // 9216 floats (B stage)
#define STAGE_FLOATS (AS_FLOATS + BS_FLOATS)   // 13824
#define STAGE_BYTES  (STAGE_FLOATS * 4)        // 55296
#define SMEM_MAIN    (STAGES * STAGE_BYTES)    // 165888

__device__ float g_hn[NB * DD];   // normalized head FC per b
__device__ float g_rp[NB * DD];   // W2 @ re_tail + b_fc per b

#define CP16(d, s) asm volatile("cp.async.cg.shared.global [%0], [%1], 16;" :: "r"(d), "l"(s) : "memory")

__device__ __forceinline__ uint32_t smem_u32(const void* p) {
    uint32_t a;
    asm("{ .reg .u64 t; cvta.to.shared.u64 t, %1; cvt.u32.u64 %0, t; }" : "=r"(a) : "l"(p));
    return a;
}
// HMMA.TF32 reads the 19 tf32 bits of each 32-bit register and ignores the low
// mantissa bits -> feed raw fp32 bits directly (CUTLASS fast-tf32 path, no cvt).
__device__ __forceinline__ void mma8(float* c, const uint32_t* a, uint32_t b0, uint32_t b1) {
    asm volatile(
        "mma.sync.aligned.m16n8k8.row.col.f32.tf32.tf32.f32 "
        "{%0,%1,%2,%3}, {%4,%5,%6,%7}, {%8,%9}, {%0,%1,%2,%3};"
        : "+f"(c[0]), "+f"(c[1]), "+f"(c[2]), "+f"(c[3])
        : "r"(a[0]), "r"(a[1]), "r"(a[2]), "r"(a[3]), "r"(b0), "r"(b1));
}

// ---------------------------------------------------------------------------
// Kernel 1: per-b head pipeline + relation-tail projection (passes, ~fast)
// ---------------------------------------------------------------------------
__global__ void k_prep(const int* __restrict__ head, const int* __restrict__ rel,
                       const float* __restrict__ ent, const float* __restrict__ remb,
                       const float* __restrict__ W,   const float* __restrict__ bfc)
{
    __shared__ float hcat[DD2];
    __shared__ float rtail[DD];
    __shared__ float hfc[DD];
    __shared__ float red[8];
    __shared__ float invn;

    int b = blockIdx.x, tid = threadIdx.x;
    int hid = head[b], r = rel[b];

    hcat[tid]      = ent [(long)hid * DD  + tid];
    hcat[DD + tid] = remb[(long)r  * DD2 + tid];
    rtail[tid]     = remb[(long)r  * DD2 + DD + tid];
    __syncthreads();

    int wid = tid >> 5, lane = tid & 31;
    for (int jj = 0; jj < 32; jj++) {
        int j = wid * 32 + jj;
        const float* wr = W + (long)j * DD2;
        float aH = 0.f, aT = 0.f;
        #pragma unroll 4
        for (int k = lane; k < DD2; k += 32) aH += wr[k]      * hcat[k];
        #pragma unroll 4
        for (int k = lane; k < DD;  k += 32) aT += wr[DD + k] * rtail[k];
        #pragma unroll
        for (int o = 16; o; o >>= 1) {
            aH += __shfl_xor_sync(0xffffffffu, aH, o);
            aT += __shfl_xor_sync(0xffffffffu, aT, o);
        }
        if (lane == 0) {
            hfc[j] = aH + bfc[j];
            g_rp[b * DD + j] = aT + bfc[j];
        }
    }
    __syncthreads();

    float v = hfc[tid];
    float sq = v * v;
    #pragma unroll
    for (int o = 16; o; o >>= 1) sq += __shfl_xor_sync(0xffffffffu, sq, o);
    if (lane == 0) red[wid] = sq;
    __syncthreads();
    if (tid == 0) {
        float s = 0.f;
        #pragma unroll
        for (int i = 0; i < 8; i++) s += red[i];
        invn = 1.0f / fmaxf(sqrtf(s), 1e-12f);
    }
    __syncthreads();
    g_hn[b * DD + tid] = v * invn;
}

// ---------------------------------------------------------------------------
// Kernel 2: mma.sync tf32 gathered GEMM (no cvt) + fused normalize/L1 epilogue
//   grid (8, 256): 128 tails/CTA, 256 threads / 8 warps (2m x 4n, 64x64 tiles)
// ---------------------------------------------------------------------------
__global__ void __launch_bounds__(256, 1) k_main(
    const int* __restrict__ tail, const float* __restrict__ ent,
    const float* __restrict__ W, float* __restrict__ out)
{
    extern __shared__ float sm[];
    __shared__ int   tidx[BM];
    __shared__ float rp_s[DD], hn_s[DD];
    __shared__ float sqp[BM][4];
    __shared__ float spp[BM][4];
    __shared__ float invb[BM];

    int tid = threadIdx.x, lane = tid & 31, wid = tid >> 5;
    int b = blockIdx.y, tile0 = blockIdx.x * BM;
    int wm = wid >> 2, wn = wid & 3;
    int lg = lane >> 2, lt = lane & 3;       // groupID, threadID_in_group

    if (tid < BM) tidx[tid] = tail[b * NNEG + tile0 + tid];
    rp_s[tid] = g_rp[b * DD + tid];
    hn_s[tid] = g_hn[b * DD + tid];
    __syncthreads();

    uint32_t sb = smem_u32(sm);

    // producer mapping: seg = 16B segment within a 128B chunk row
    int seg = tid & 7;
    int r0  = tid >> 3;                       // 0..31

    // hoist gather base pointers
    const float* aBase[4];
    #pragma unroll
    for (int i = 0; i < 4; i++)
        aBase[i] = ent + (long)tidx[r0 + 32 * i] * DD + seg * 4;
    const float* bBase[8];
    #pragma unroll
    for (int i = 0; i < 8; i++)
        bBase[i] = W + (long)(r0 + 32 * i) * DD2 + seg * 4;

    float acc[4][8][4];
    #pragma unroll
    for (int i = 0; i < 4; i++)
        #pragma unroll
        for (int t = 0; t < 8; t++)
            #pragma unroll
            for (int q = 0; q < 4; q++) acc[i][t][q] = 0.f;

    #define ISSUE(c) do {                                                       \
        uint32_t _st = sb + (uint32_t)((c) % STAGES) * STAGE_BYTES;             \
        _Pragma("unroll")                                                       \
        for (int _i = 0; _i < 4; _i++)                                          \
            CP16(_st + (uint32_t)((r0 + 32 * _i) * 144 + seg * 16),             \
                 aBase[_i] + (c) * BK);                                         \
        _Pragma("unroll")                                                       \
        for (int _i = 0; _i < 8; _i++)                                          \
            CP16(_st + (uint32_t)(18432 + (r0 + 32 * _i) * 144 + seg * 16),     \
                 bBase[_i] + (c) * BK);                                         \
        asm volatile("cp.async.commit_group;" ::: "memory");                    \
    } while (0)

    ISSUE(0);
    ISSUE(1);

    #pragma unroll
    for (int c = 0; c < 8; c++) {
        if (c < 7) asm volatile("cp.async.wait_group 1;" ::: "memory");
        else       asm volatile("cp.async.wait_group 0;" ::: "memory");
        __syncthreads();
        if (c + 2 < 8) ISSUE(c + 2);

        const uint32_t* Asp = (const uint32_t*)(sm + (c % STAGES) * STAGE_FLOATS);
        const uint32_t* Bsp = Asp + AS_FLOATS;

        #pragma unroll
        for (int ks = 0; ks < 4; ks++) {
            int k0 = ks * 8 + lt;
            uint32_t a[4][4];
            #pragma unroll
            for (int i = 0; i < 4; i++) {
                int r = wm * 64 + i * 16 + lg;
                a[i][0] = Asp[r * 36 + k0];
                a[i][1] = Asp[(r + 8) * 36 + k0];
                a[i][2] = Asp[r * 36 + k0 + 4];
                a[i][3] = Asp[(r + 8) * 36 + k0 + 4];
            }
            #pragma unroll
            for (int t = 0; t < 8; t++) {
                int n = wn * 64 + t * 8 + lg;
                uint32_t b0 = Bsp[n * 36 + k0];
                uint32_t b1 = Bsp[n * 36 + k0 + 4];
                #pragma unroll
                for (int i = 0; i < 4; i++) mma8(acc[i][t], a[i], b0, b1);
            }
        }
    }
    #undef ISSUE

    // ---- epilogue ----
    #pragma unroll
    for (int i = 0; i < 4; i++) {
        #pragma unroll
        for (int rh = 0; rh < 2; rh++) {
            float s = 0.f;
            #pragma unroll
            for (int t = 0; t < 8; t++) {
                int n0 = wn * 64 + t * 8 + 2 * lt;
                float c0 = acc[i][t][rh * 2 + 0] + rp_s[n0];
                float c1 = acc[i][t][rh * 2 + 1] + rp_s[n0 + 1];
                s += c0 * c0 + c1 * c1;
            }
            s += __shfl_xor_sync(0xffffffffu, s, 1);
            s += __shfl_xor_sync(0xffffffffu, s, 2);
            if (lt == 0) sqp[wm * 64 + i * 16 + rh * 8 + lg][wn] = s;
        }
    }
    __syncthreads();
    if (tid < BM) {
        float sq = sqp[tid][0] + sqp[tid][1] + sqp[tid][2] + sqp[tid][3];
        invb[tid] = 1.0f / fmaxf(sqrtf(sq), 1e-12f);
    }
    __syncthreads();

    #pragma unroll
    for (int i = 0; i < 4; i++) {
        #pragma unroll
        for (int rh = 0; rh < 2; rh++) {
            int row = wm * 64 + i * 16 + rh * 8 + lg;
            float inv = invb[row];
            float s = 0.f;
            #pragma unroll
            for (int t = 0; t < 8; t++) {
                int n0 = wn * 64 + t * 8 + 2 * lt;
                float t0 = (acc[i][t][rh * 2 + 0] + rp_s[n0])     * inv;
                float t1 = (acc[i][t][rh * 2 + 1] + rp_s[n0 + 1]) * inv;
                s += fabsf(hn_s[n0] - t0) + fabsf(hn_s[n0 + 1] - t1);
            }
            s += __shfl_xor_sync(0xffffffffu, s, 1);
            s += __shfl_xor_sync(0xffffffffu, s, 2);
            if (lt == 0) spp[row][wn] = s;
        }
    }
    __syncthreads();
    if (tid < BM)
        out[b * NNEG + tile0 + tid] =
            12.0f - (spp[tid][0] + spp[tid][1] + spp[tid][2] + spp[tid][3]);
}

// ---------------------------------------------------------------------------
extern "C" void kernel_launch(void* const* d_in, const int* in_sizes, int n_in,
                              void* d_out, int out_size)
{
    const int*   head = (const int*)  d_in[0];
    const int*   tail = (const int*)  d_in[1];
    const int*   rel  = (const int*)  d_in[2];
    const float* ent  = (const float*)d_in[3];
    const float* remb = (const float*)d_in[4];
    const float* W    = (const float*)d_in[5];
    const float* bfc  = (const float*)d_in[6];
    float* out = (float*)d_out;

    cudaFuncSetAttribute(k_main, cudaFuncAttributeMaxDynamicSharedMemorySize, SMEM_MAIN);

    k_prep<<<NB, 256>>>(head, rel, ent, remb, W, bfc);
    k_main<<<dim3(NNEG / BM, NB), 256, SMEM_MAIN>>>(tail, ent, W, out);
}

// round 5
// speedup vs baseline: 1.4028x; 1.4028x over previous
#include <cuda_runtime.h>
#include <cstdint>

#define NB    256
#define NNEG  1024
#define DD    256
#define DD2   512
#define BM    128
#define BK    32
#define STAGES 3
#define AS_FLOATS (BM * 36)                    // 4608 floats (A stage)
#define BS_FLOATS (DD * 36)                    // 9216 floats (B stage)
#define STAGE_FLOATS (AS_FLOATS + BS_FLOATS)   // 13824
#define STAGE_BYTES  (STAGE_FLOATS * 4)        // 55296
#define SMEM_MAIN    (STAGES * STAGE_BYTES)    // 165888

__device__ float g_hn[NB * DD];   // normalized head FC per b
__device__ float g_rp[NB * DD];   // W2 @ re_tail + b_fc per b
__device__ float g_Wt[DD * DD];   // entity half of W, tf32-pre-rounded, [n][k] stride 256

#define CP16(d, s) asm volatile("cp.async.cg.shared.global [%0], [%1], 16;" :: "r"(d), "l"(s) : "memory")

__device__ __forceinline__ uint32_t smem_u32(const void* p) {
    uint32_t a;
    asm("{ .reg .u64 t; cvta.to.shared.u64 t, %1; cvt.u32.u64 %0, t; }" : "=r"(a) : "l"(p));
    return a;
}
__device__ __forceinline__ uint32_t f2tf32(float f) {
    uint32_t u;
    asm("cvt.rna.tf32.f32 %0, %1;" : "=r"(u) : "f"(f));
    return u;
}
__device__ __forceinline__ void mma8(float* c, const uint32_t* a, uint32_t b0, uint32_t b1) {
    asm volatile(
        "mma.sync.aligned.m16n8k8.row.col.f32.tf32.tf32.f32 "
        "{%0,%1,%2,%3}, {%4,%5,%6,%7}, {%8,%9}, {%0,%1,%2,%3};"
        : "+f"(c[0]), "+f"(c[1]), "+f"(c[2]), "+f"(c[3])
        : "r"(a[0]), "r"(a[1]), "r"(a[2]), "r"(a[3]), "r"(b0), "r"(b1));
}

// ---------------------------------------------------------------------------
// Kernel 0: pre-round the entity half of W_fc to tf32 (once; B needs no cvt)
// ---------------------------------------------------------------------------
__global__ void k_cvtW(const float* __restrict__ W) {
    int i = blockIdx.x * 256 + threadIdx.x;   // i = n*256 + k over 65536
    int n = i >> 8, k = i & 255;
    g_Wt[i] = __uint_as_float(f2tf32(W[n * DD2 + k]));
}

// ---------------------------------------------------------------------------
// Kernel 1: per-b head pipeline + relation-tail projection (passes)
// ---------------------------------------------------------------------------
__global__ void k_prep(const int* __restrict__ head, const int* __restrict__ rel,
                       const float* __restrict__ ent, const float* __restrict__ remb,
                       const float* __restrict__ W,   const float* __restrict__ bfc)
{
    __shared__ float hcat[DD2];
    __shared__ float rtail[DD];
    __shared__ float hfc[DD];
    __shared__ float red[8];
    __shared__ float invn;

    int b = blockIdx.x, tid = threadIdx.x;
    int hid = head[b], r = rel[b];

    hcat[tid]      = ent [(long)hid * DD  + tid];
    hcat[DD + tid] = remb[(long)r  * DD2 + tid];
    rtail[tid]     = remb[(long)r  * DD2 + DD + tid];
    __syncthreads();

    int wid = tid >> 5, lane = tid & 31;
    for (int jj = 0; jj < 32; jj++) {
        int j = wid * 32 + jj;
        const float* wr = W + (long)j * DD2;
        float aH = 0.f, aT = 0.f;
        #pragma unroll 4
        for (int k = lane; k < DD2; k += 32) aH += wr[k]      * hcat[k];
        #pragma unroll 4
        for (int k = lane; k < DD;  k += 32) aT += wr[DD + k] * rtail[k];
        #pragma unroll
        for (int o = 16; o; o >>= 1) {
            aH += __shfl_xor_sync(0xffffffffu, aH, o);
            aT += __shfl_xor_sync(0xffffffffu, aT, o);
        }
        if (lane == 0) {
            hfc[j] = aH + bfc[j];
            g_rp[b * DD + j] = aT + bfc[j];
        }
    }
    __syncthreads();

    float v = hfc[tid];
    float sq = v * v;
    #pragma unroll
    for (int o = 16; o; o >>= 1) sq += __shfl_xor_sync(0xffffffffu, sq, o);
    if (lane == 0) red[wid] = sq;
    __syncthreads();
    if (tid == 0) {
        float s = 0.f;
        #pragma unroll
        for (int i = 0; i < 8; i++) s += red[i];
        invn = 1.0f / fmaxf(sqrtf(s), 1e-12f);
    }
    __syncthreads();
    g_hn[b * DD + tid] = v * invn;
}

// ---------------------------------------------------------------------------
// Kernel 2: tf32 mma.sync gathered GEMM + fused epilogue
//   512 threads / 16 warps (4m x 4n), warp tile 32x64, CTA tile 128x256.
// ---------------------------------------------------------------------------
__global__ void __launch_bounds__(512, 1) k_main(
    const int* __restrict__ tail, const float* __restrict__ ent,
    float* __restrict__ out)
{
    extern __shared__ float sm[];
    __shared__ int   tidx[BM];
    __shared__ float rp_s[DD], hn_s[DD];
    __shared__ float sqp[BM][4];
    __shared__ float spp[BM][4];
    __shared__ float invb[BM];

    int tid = threadIdx.x, lane = tid & 31, wid = tid >> 5;
    int b = blockIdx.y, tile0 = blockIdx.x * BM;
    int wm = wid >> 2, wn = wid & 3;           // 4 x 4 warp grid
    int lg = lane >> 2, lt = lane & 3;

    if (tid < BM) tidx[tid] = tail[b * NNEG + tile0 + tid];
    if (tid < DD) { rp_s[tid] = g_rp[b * DD + tid]; hn_s[tid] = g_hn[b * DD + tid]; }
    __syncthreads();

    uint32_t sb = smem_u32(sm);

    // producer mapping: 512 threads; seg = tid&7 (16B segment), r0 = tid>>3 (0..63)
    int seg = tid & 7;
    int r0  = tid >> 3;

    const float* aBase[2];
    #pragma unroll
    for (int i = 0; i < 2; i++)
        aBase[i] = ent + (long)tidx[r0 + 64 * i] * DD + seg * 4;
    const float* bBase[4];
    #pragma unroll
    for (int i = 0; i < 4; i++)
        bBase[i] = g_Wt + (long)(r0 + 64 * i) * DD + seg * 4;

    float acc[2][8][4];
    #pragma unroll
    for (int i = 0; i < 2; i++)
        #pragma unroll
        for (int t = 0; t < 8; t++)
            #pragma unroll
            for (int q = 0; q < 4; q++) acc[i][t][q] = 0.f;

    #define ISSUE(c) do {                                                       \
        uint32_t _st = sb + (uint32_t)((c) % STAGES) * STAGE_BYTES;             \
        _Pragma("unroll")                                                       \
        for (int _i = 0; _i < 2; _i++)                                          \
            CP16(_st + (uint32_t)((r0 + 64 * _i) * 144 + seg * 16),             \
                 aBase[_i] + (c) * BK);                                         \
        _Pragma("unroll")                                                       \
        for (int _i = 0; _i < 4; _i++)                                          \
            CP16(_st + (uint32_t)(18432 + (r0 + 64 * _i) * 144 + seg * 16),     \
                 bBase[_i] + (c) * BK);                                         \
        asm volatile("cp.async.commit_group;" ::: "memory");                    \
    } while (0)

    ISSUE(0);
    ISSUE(1);

    #pragma unroll
    for (int c = 0; c < 8; c++) {
        if (c < 7) asm volatile("cp.async.wait_group 1;" ::: "memory");
        else       asm volatile("cp.async.wait_group 0;" ::: "memory");
        __syncthreads();
        if (c + 2 < 8) ISSUE(c + 2);

        const uint32_t* Asp = (const uint32_t*)(sm + (c % STAGES) * STAGE_FLOATS);
        const uint32_t* Bsp = Asp + AS_FLOATS;

        #pragma unroll
        for (int ks = 0; ks < 4; ks++) {
            int k0 = ks * 8 + lt;
            uint32_t a[2][4];
            #pragma unroll
            for (int i = 0; i < 2; i++) {
                int r = wm * 32 + i * 16 + lg;
                a[i][0] = f2tf32(__uint_as_float(Asp[r * 36 + k0]));
                a[i][1] = f2tf32(__uint_as_float(Asp[(r + 8) * 36 + k0]));
                a[i][2] = f2tf32(__uint_as_float(Asp[r * 36 + k0 + 4]));
                a[i][3] = f2tf32(__uint_as_float(Asp[(r + 8) * 36 + k0 + 4]));
            }
            #pragma unroll
            for (int t = 0; t < 8; t++) {
                int n = wn * 64 + t * 8 + lg;
                uint32_t b0 = Bsp[n * 36 + k0];        // pre-rounded, no cvt
                uint32_t b1 = Bsp[n * 36 + k0 + 4];
                #pragma unroll
                for (int i = 0; i < 2; i++) mma8(acc[i][t], a[i], b0, b1);
            }
        }
    }
    #undef ISSUE

    // ---- epilogue ----
    #pragma unroll
    for (int i = 0; i < 2; i++) {
        #pragma unroll
        for (int rh = 0; rh < 2; rh++) {
            float s = 0.f;
            #pragma unroll
            for (int t = 0; t < 8; t++) {
                int n0 = wn * 64 + t * 8 + 2 * lt;
                float c0 = acc[i][t][rh * 2 + 0] + rp_s[n0];
                float c1 = acc[i][t][rh * 2 + 1] + rp_s[n0 + 1];
                s += c0 * c0 + c1 * c1;
            }
            s += __shfl_xor_sync(0xffffffffu, s, 1);
            s += __shfl_xor_sync(0xffffffffu, s, 2);
            if (lt == 0) sqp[wm * 32 + i * 16 + rh * 8 + lg][wn] = s;
        }
    }
    __syncthreads();
    if (tid < BM) {
        float sq = sqp[tid][0] + sqp[tid][1] + sqp[tid][2] + sqp[tid][3];
        invb[tid] = 1.0f / fmaxf(sqrtf(sq), 1e-12f);
    }
    __syncthreads();

    #pragma unroll
    for (int i = 0; i < 2; i++) {
        #pragma unroll
        for (int rh = 0; rh < 2; rh++) {
            int row = wm * 32 + i * 16 + rh * 8 + lg;
            float inv = invb[row];
            float s = 0.f;
            #pragma unroll
            for (int t = 0; t < 8; t++) {
                int n0 = wn * 64 + t * 8 + 2 * lt;
                float t0 = (acc[i][t][rh * 2 + 0] + rp_s[n0])     * inv;
                float t1 = (acc[i][t][rh * 2 + 1] + rp_s[n0 + 1]) * inv;
                s += fabsf(hn_s[n0] - t0) + fabsf(hn_s[n0 + 1] - t1);
            }
            s += __shfl_xor_sync(0xffffffffu, s, 1);
            s += __shfl_xor_sync(0xffffffffu, s, 2);
            if (lt == 0) spp[row][wn] = s;
        }
    }
    __syncthreads();
    if (tid < BM)
        out[b * NNEG + tile0 + tid] =
            12.0f - (spp[tid][0] + spp[tid][1] + spp[tid][2] + spp[tid][3]);
}

// ---------------------------------------------------------------------------
extern "C" void kernel_launch(void* const* d_in, const int* in_sizes, int n_in,
                              void* d_out, int out_size)
{
    const int*   head = (const int*)  d_in[0];
    const int*   tail = (const int*)  d_in[1];
    const int*   rel  = (const int*)  d_in[2];
    const float* ent  = (const float*)d_in[3];
    const float* remb = (const float*)d_in[4];
    const float* W    = (const float*)d_in[5];
    const float* bfc  = (const float*)d_in[6];
    float* out = (float*)d_out;

    cudaFuncSetAttribute(k_main, cudaFuncAttributeMaxDynamicSharedMemorySize, SMEM_MAIN);

    k_cvtW<<<DD, 256>>>(W);
    k_prep<<<NB, 256>>>(head, rel, ent, remb, W, bfc);
    k_main<<<dim3(NNEG / BM, NB), 512, SMEM_MAIN>>>(tail, ent, out);
}

// round 7
// speedup vs baseline: 1.8125x; 1.2921x over previous
#include <cuda_runtime.h>
#include <cuda_fp16.h>
#include <cstdint>

#define NB    256
#define NNEG  1024
#define DD    256
#define DD2   512
#define BM    128
#define BK    32                     // fp16 k per chunk
#define NCH   8
#define RPAD  40                     // fp16 per padded row (80B, stride 20 banks)
#define A_STAGE_B (BM  * RPAD * 2)   // 10240
#define B_STAGE_B (DD  * RPAD * 2)   // 20480
#define STAGE_B   (A_STAGE_B + B_STAGE_B)  // 30720
#define SMEM_MAIN (4 * STAGE_B)            // 122880

__device__ float  g_hn[NB * DD];
__device__ float  g_rp[NB * DD];
__device__ __half g_Wh[DD * DD];     // entity half of W, fp16, [n][k]

#define CP16(d, s) asm volatile("cp.async.cg.shared.global [%0], [%1], 16;" :: "r"(d), "l"(s) : "memory")

__device__ __forceinline__ uint32_t smem_u32(const void* p) {
    uint32_t a;
    asm("{ .reg .u64 t; cvta.to.shared.u64 t, %1; cvt.u32.u64 %0, t; }" : "=r"(a) : "l"(p));
    return a;
}
__device__ __forceinline__ uint32_t h2_bits(__half2 h) {
    return *reinterpret_cast<uint32_t*>(&h);
}
__device__ __forceinline__ void mma16(float* c, const uint32_t* a, uint32_t b0, uint32_t b1) {
    asm volatile(
        "mma.sync.aligned.m16n8k16.row.col.f32.f16.f16.f32 "
        "{%0,%1,%2,%3}, {%4,%5,%6,%7}, {%8,%9}, {%0,%1,%2,%3};"
        : "+f"(c[0]), "+f"(c[1]), "+f"(c[2]), "+f"(c[3])
        : "r"(a[0]), "r"(a[1]), "r"(a[2]), "r"(a[3]), "r"(b0), "r"(b1));
}

// ---------------------------------------------------------------------------
__global__ void k_cvtW(const float* __restrict__ W) {
    int i = blockIdx.x * 256 + threadIdx.x;       // 65536 elements
    int n = i >> 8, k = i & 255;
    g_Wh[i] = __float2half_rn(W[n * DD2 + k]);
}

// ---------------------------------------------------------------------------
__global__ void k_prep(const int* __restrict__ head, const int* __restrict__ rel,
                       const float* __restrict__ ent, const float* __restrict__ remb,
                       const float* __restrict__ W,   const float* __restrict__ bfc)
{
    __shared__ float hcat[DD2];
    __shared__ float rtail[DD];
    __shared__ float hfc[DD];
    __shared__ float red[8];
    __shared__ float invn;

    int b = blockIdx.x, tid = threadIdx.x;
    int hid = head[b], r = rel[b];

    hcat[tid]      = ent [(long)hid * DD  + tid];
    hcat[DD + tid] = remb[(long)r  * DD2 + tid];
    rtail[tid]     = remb[(long)r  * DD2 + DD + tid];
    __syncthreads();

    int wid = tid >> 5, lane = tid & 31;
    for (int jj = 0; jj < 32; jj++) {
        int j = wid * 32 + jj;
        const float* wr = W + (long)j * DD2;
        float aH = 0.f, aT = 0.f;
        #pragma unroll 4
        for (int k = lane; k < DD2; k += 32) aH += wr[k]      * hcat[k];
        #pragma unroll 4
        for (int k = lane; k < DD;  k += 32) aT += wr[DD + k] * rtail[k];
        #pragma unroll
        for (int o = 16; o; o >>= 1) {
            aH += __shfl_xor_sync(0xffffffffu, aH, o);
            aT += __shfl_xor_sync(0xffffffffu, aT, o);
        }
        if (lane == 0) {
            hfc[j] = aH + bfc[j];
            g_rp[b * DD + j] = aT + bfc[j];
        }
    }
    __syncthreads();

    float v = hfc[tid];
    float sq = v * v;
    #pragma unroll
    for (int o = 16; o; o >>= 1) sq += __shfl_xor_sync(0xffffffffu, sq, o);
    if (lane == 0) red[wid] = sq;
    __syncthreads();
    if (tid == 0) {
        float s = 0.f;
        #pragma unroll
        for (int i = 0; i < 8; i++) s += red[i];
        invn = 1.0f / fmaxf(sqrtf(s), 1e-12f);
    }
    __syncthreads();
    g_hn[b * DD + tid] = v * invn;
}

// ---------------------------------------------------------------------------
// fp16 mma.sync gathered GEMM + fused epilogue.
//   512 threads / 16 warps (4m x 4n), warp tile 32x64, CTA tile 128x256.
//   A: LDG fp32 -> cvt fp16 -> STS (2 chunks ahead). B: cp.async fp16 table.
// ---------------------------------------------------------------------------
__global__ void __launch_bounds__(512, 1) k_main(
    const int* __restrict__ tail, const float* __restrict__ ent,
    float* __restrict__ out)
{
    extern __shared__ char smc[];
    __shared__ int   tidx[BM];
    __shared__ float rp_s[DD], hn_s[DD];
    __shared__ float sqp[BM][4];
    __shared__ float spp[BM][4];
    __shared__ float invb[BM];

    int tid = threadIdx.x, lane = tid & 31, wid = tid >> 5;
    int b = blockIdx.y, tile0 = blockIdx.x * BM;
    int wm = wid >> 2, wn = wid & 3;
    int lg = lane >> 2, lt = lane & 3;

    if (tid < BM) tidx[tid] = tail[b * NNEG + tile0 + tid];
    if (tid < DD) { rp_s[tid] = g_rp[b * DD + tid]; hn_s[tid] = g_hn[b * DD + tid]; }
    __syncthreads();

    uint32_t sb = smem_u32(smc);

    // A producer: row = tid>>2 (0..127), seg = tid&3 covers fp32 cols seg*8..+7
    int arow = tid >> 2, aseg = tid & 3;
    const float* aSrc = ent + (long)tidx[arow] * DD + aseg * 8;
    uint32_t aOff = (uint32_t)(arow * (RPAD * 2) + aseg * 16);

    // B producer: row = tid>>1 (0..255), two 16B segs {tid&1, tid&1+2}
    int brow = tid >> 1, bs0 = tid & 1, bs1 = bs0 + 2;
    const __half* bSrc = g_Wh + (long)brow * DD;
    uint32_t bDst = sb + (uint32_t)(A_STAGE_B + brow * (RPAD * 2));

    float4 regA[2][2];
    #define LDGA(c, buf) do {                                   \
        regA[buf][0] = *(const float4*)(aSrc + (c) * BK);       \
        regA[buf][1] = *(const float4*)(aSrc + (c) * BK + 4);   \
    } while (0)
    #define STSA(c, buf) do {                                   \
        __half2 h0 = __floats2half2_rn(regA[buf][0].x, regA[buf][0].y); \
        __half2 h1 = __floats2half2_rn(regA[buf][0].z, regA[buf][0].w); \
        __half2 h2 = __floats2half2_rn(regA[buf][1].x, regA[buf][1].y); \
        __half2 h3 = __floats2half2_rn(regA[buf][1].z, regA[buf][1].w); \
        uint4 u;                                                \
        u.x = h2_bits(h0); u.y = h2_bits(h1);                   \
        u.z = h2_bits(h2); u.w = h2_bits(h3);                   \
        *(uint4*)(smc + (((c) & 3) * STAGE_B) + aOff) = u;      \
    } while (0)
    #define CPB(c) do {                                                   \
        uint32_t _d = bDst + ((c) & 3) * STAGE_B;                         \
        CP16(_d + bs0 * 16, bSrc + (c) * BK + bs0 * 8);                   \
        CP16(_d + bs1 * 16, bSrc + (c) * BK + bs1 * 8);                   \
        asm volatile("cp.async.commit_group;" ::: "memory");              \
    } while (0)

    float acc[2][8][4];
    #pragma unroll
    for (int i = 0; i < 2; i++)
        #pragma unroll
        for (int t = 0; t < 8; t++)
            #pragma unroll
            for (int q = 0; q < 4; q++) acc[i][t][q] = 0.f;

    LDGA(0, 0); CPB(0);
    LDGA(1, 1); CPB(1);

    #pragma unroll
    for (int c = 0; c < NCH; c++) {
        if (c < NCH - 1) asm volatile("cp.async.wait_group 1;" ::: "memory");
        else             asm volatile("cp.async.wait_group 0;" ::: "memory");
        STSA(c, c & 1);
        __syncthreads();
        if (c + 2 < NCH) { LDGA(c + 2, c & 1); CPB(c + 2); }

        const uint32_t* Asp = (const uint32_t*)(smc + (c & 3) * STAGE_B);
        const uint32_t* Bsp = (const uint32_t*)(smc + (c & 3) * STAGE_B + A_STAGE_B);

        #pragma unroll
        for (int ks = 0; ks < 2; ks++) {
            int kb = ks * 8 + lt;              // u32 index within padded row
            uint32_t a[2][4];
            #pragma unroll
            for (int i = 0; i < 2; i++) {
                int r = wm * 32 + i * 16 + lg;
                a[i][0] = Asp[r * 20 + kb];
                a[i][1] = Asp[(r + 8) * 20 + kb];
                a[i][2] = Asp[r * 20 + kb + 4];
                a[i][3] = Asp[(r + 8) * 20 + kb + 4];
            }
            #pragma unroll
            for (int t = 0; t < 8; t++) {
                int n = wn * 64 + t * 8 + lg;
                uint32_t b0 = Bsp[n * 20 + kb];
                uint32_t b1 = Bsp[n * 20 + kb + 4];
                #pragma unroll
                for (int i = 0; i < 2; i++) mma16(acc[i][t], a[i], b0, b1);
            }
        }
    }
    #undef LDGA
    #undef STSA
    #undef CPB

    // ---- epilogue ----
    #pragma unroll
    for (int i = 0; i < 2; i++) {
        #pragma unroll
        for (int rh = 0; rh < 2; rh++) {
            float s = 0.f;
            #pragma unroll
            for (int t = 0; t < 8; t++) {
                int n0 = wn * 64 + t * 8 + 2 * lt;
                float c0 = acc[i][t][rh * 2 + 0] + rp_s[n0];
                float c1 = acc[i][t][rh * 2 + 1] + rp_s[n0 + 1];
                s += c0 * c0 + c1 * c1;
            }
            s += __shfl_xor_sync(0xffffffffu, s, 1);
            s += __shfl_xor_sync(0xffffffffu, s, 2);
            if (lt == 0) sqp[wm * 32 + i * 16 + rh * 8 + lg][wn] = s;
        }
    }
    __syncthreads();
    if (tid < BM) {
        float sq = sqp[tid][0] + sqp[tid][1] + sqp[tid][2] + sqp[tid][3];
        invb[tid] = 1.0f / fmaxf(sqrtf(sq), 1e-12f);
    }
    __syncthreads();

    #pragma unroll
    for (int i = 0; i < 2; i++) {
        #pragma unroll
        for (int rh = 0; rh < 2; rh++) {
            int row = wm * 32 + i * 16 + rh * 8 + lg;
            float inv = invb[row];
            float s = 0.f;
            #pragma unroll
            for (int t = 0; t < 8; t++) {
                int n0 = wn * 64 + t * 8 + 2 * lt;
                float t0 = (acc[i][t][rh * 2 + 0] + rp_s[n0])     * inv;
                float t1 = (acc[i][t][rh * 2 + 1] + rp_s[n0 + 1]) * inv;
                s += fabsf(hn_s[n0] - t0) + fabsf(hn_s[n0 + 1] - t1);
            }
            s += __shfl_xor_sync(0xffffffffu, s, 1);
            s += __shfl_xor_sync(0xffffffffu, s, 2);
            if (lt == 0) spp[row][wn] = s;
        }
    }
    __syncthreads();
    if (tid < BM)
        out[b * NNEG + tile0 + tid] =
            12.0f - (spp[tid][0] + spp[tid][1] + spp[tid][2] + spp[tid][3]);
}

// ---------------------------------------------------------------------------
extern "C" void kernel_launch(void* const* d_in, const int* in_sizes, int n_in,
                              void* d_out, int out_size)
{
    const int*   head = (const int*)  d_in[0];
    const int*   tail = (const int*)  d_in[1];
    const int*   rel  = (const int*)  d_in[2];
    const float* ent  = (const float*)d_in[3];
    const float* remb = (const float*)d_in[4];
    const float* W    = (const float*)d_in[5];
    const float* bfc  = (const float*)d_in[6];
    float* out = (float*)d_out;

    cudaFuncSetAttribute(k_main, cudaFuncAttributeMaxDynamicSharedMemorySize, SMEM_MAIN);

    k_cvtW<<<DD, 256>>>(W);
    k_prep<<<NB, 256>>>(head, rel, ent, remb, W, bfc);
    k_main<<<dim3(NNEG / BM, NB), 512, SMEM_MAIN>>>(tail, ent, out);
}

// round 8
// speedup vs baseline: 1.9437x; 1.0724x over previous
#include <cuda_runtime.h>
#include <cuda_fp16.h>
#include <cstdint>

#define NB    256
#define NNEG  1024
#define DD    256
#define DD2   512
#define BM    128
#define BK    32                     // fp16 k per chunk
#define NCH   8
#define RPAD  40                     // fp16 per padded row (80B, stride 20 banks)
#define A_STAGE_B (BM  * RPAD * 2)   // 10240
#define B_STAGE_B (DD  * RPAD * 2)   // 20480
#define STAGE_B   (A_STAGE_B + B_STAGE_B)  // 30720
#define SMEM_MAIN (4 * STAGE_B)            // 122880

__device__ float  g_hn[NB * DD];
__device__ float  g_rp[NB * DD];
__device__ __half g_Wh[DD * DD];     // entity half of W, fp16, [n][k]

#define CP16(d, s) asm volatile("cp.async.cg.shared.global [%0], [%1], 16;" :: "r"(d), "l"(s) : "memory")
#define LDSM4(r0, r1, r2, r3, a) asm volatile( \
    "ldmatrix.sync.aligned.m8n8.x4.shared.b16 {%0,%1,%2,%3}, [%4];" \
    : "=r"(r0), "=r"(r1), "=r"(r2), "=r"(r3) : "r"(a))

__device__ __forceinline__ uint32_t smem_u32(const void* p) {
    uint32_t a;
    asm("{ .reg .u64 t; cvta.to.shared.u64 t, %1; cvt.u32.u64 %0, t; }" : "=r"(a) : "l"(p));
    return a;
}
__device__ __forceinline__ uint32_t h2_bits(__half2 h) {
    return *reinterpret_cast<uint32_t*>(&h);
}
__device__ __forceinline__ void mma16(float* c, const uint32_t* a, uint32_t b0, uint32_t b1) {
    asm volatile(
        "mma.sync.aligned.m16n8k16.row.col.f32.f16.f16.f32 "
        "{%0,%1,%2,%3}, {%4,%5,%6,%7}, {%8,%9}, {%0,%1,%2,%3};"
        : "+f"(c[0]), "+f"(c[1]), "+f"(c[2]), "+f"(c[3])
        : "r"(a[0]), "r"(a[1]), "r"(a[2]), "r"(a[3]), "r"(b0), "r"(b1));
}

// ---------------------------------------------------------------------------
__global__ void k_cvtW(const float* __restrict__ W) {
    int i = blockIdx.x * 256 + threadIdx.x;
    int n = i >> 8, k = i & 255;
    g_Wh[i] = __float2half_rn(W[n * DD2 + k]);
}

// ---------------------------------------------------------------------------
__global__ void k_prep(const int* __restrict__ head, const int* __restrict__ rel,
                       const float* __restrict__ ent, const float* __restrict__ remb,
                       const float* __restrict__ W,   const float* __restrict__ bfc)
{
    __shared__ float hcat[DD2];
    __shared__ float rtail[DD];
    __shared__ float hfc[DD];
    __shared__ float red[8];
    __shared__ float invn;

    int b = blockIdx.x, tid = threadIdx.x;
    int hid = head[b], r = rel[b];

    hcat[tid]      = ent [(long)hid * DD  + tid];
    hcat[DD + tid] = remb[(long)r  * DD2 + tid];
    rtail[tid]     = remb[(long)r  * DD2 + DD + tid];
    __syncthreads();

    int wid = tid >> 5, lane = tid & 31;
    for (int jj = 0; jj < 32; jj++) {
        int j = wid * 32 + jj;
        const float* wr = W + (long)j * DD2;
        float aH = 0.f, aT = 0.f;
        #pragma unroll 4
        for (int k = lane; k < DD2; k += 32) aH += wr[k]      * hcat[k];
        #pragma unroll 4
        for (int k = lane; k < DD;  k += 32) aT += wr[DD + k] * rtail[k];
        #pragma unroll
        for (int o = 16; o; o >>= 1) {
            aH += __shfl_xor_sync(0xffffffffu, aH, o);
            aT += __shfl_xor_sync(0xffffffffu, aT, o);
        }
        if (lane == 0) {
            hfc[j] = aH + bfc[j];
            g_rp[b * DD + j] = aT + bfc[j];
        }
    }
    __syncthreads();

    float v = hfc[tid];
    float sq = v * v;
    #pragma unroll
    for (int o = 16; o; o >>= 1) sq += __shfl_xor_sync(0xffffffffu, sq, o);
    if (lane == 0) red[wid] = sq;
    __syncthreads();
    if (tid == 0) {
        float s = 0.f;
        #pragma unroll
        for (int i = 0; i < 8; i++) s += red[i];
        invn = 1.0f / fmaxf(sqrtf(s), 1e-12f);
    }
    __syncthreads();
    g_hn[b * DD + tid] = v * invn;
}

// ---------------------------------------------------------------------------
// fp16 mma.sync + ldmatrix gathered GEMM + fused epilogue.
//   512 threads / 16 warps (4m x 4n), warp tile 32x64, CTA tile 128x256.
// ---------------------------------------------------------------------------
__global__ void __launch_bounds__(512, 1) k_main(
    const int* __restrict__ tail, const float* __restrict__ ent,
    float* __restrict__ out)
{
    extern __shared__ char smc[];
    __shared__ int   tidx[BM];
    __shared__ float rp_s[DD], hn_s[DD];
    __shared__ float sqp[BM][4];
    __shared__ float spp[BM][4];
    __shared__ float invb[BM];

    int tid = threadIdx.x, lane = tid & 31, wid = tid >> 5;
    int b = blockIdx.y, tile0 = blockIdx.x * BM;
    int wm = wid >> 2, wn = wid & 3;
    int lg = lane >> 2, lt = lane & 3;

    if (tid < BM) tidx[tid] = tail[b * NNEG + tile0 + tid];
    if (tid < DD) { rp_s[tid] = g_rp[b * DD + tid]; hn_s[tid] = g_hn[b * DD + tid]; }
    __syncthreads();

    uint32_t sb = smem_u32(smc);

    // ---- producers ----
    int arow = tid >> 2, aseg = tid & 3;
    const float* aSrc = ent + (long)tidx[arow] * DD + aseg * 8;
    uint32_t aOff = (uint32_t)(arow * (RPAD * 2) + aseg * 16);

    int brow = tid >> 1, bs0 = tid & 1, bs1 = bs0 + 2;
    const __half* bSrc = g_Wh + (long)brow * DD;
    uint32_t bDst = sb + (uint32_t)(A_STAGE_B + brow * (RPAD * 2));

    // ---- ldmatrix lane bases (ks=0, stage 0) ----
    uint32_t aLm[2], bLm[4];
    #pragma unroll
    for (int i = 0; i < 2; i++) {
        int row = wm * 32 + i * 16 + (lane & 7) + ((lane >> 3) & 1) * 8;
        int kc  = ((lane >> 4) & 1) * 8;
        aLm[i] = sb + (uint32_t)(row * (RPAD * 2) + kc * 2);
    }
    #pragma unroll
    for (int p = 0; p < 4; p++) {
        int rn = wn * 64 + p * 16 + (lane & 7) + ((lane >> 4) & 1) * 8;
        int kc = ((lane >> 3) & 1) * 8;
        bLm[p] = sb + (uint32_t)(A_STAGE_B + rn * (RPAD * 2) + kc * 2);
    }

    float4 regA[2][2];
    #define LDGA(c, buf) do {                                   \
        regA[buf][0] = *(const float4*)(aSrc + (c) * BK);       \
        regA[buf][1] = *(const float4*)(aSrc + (c) * BK + 4);   \
    } while (0)
    #define STSA(c, buf) do {                                   \
        __half2 h0 = __floats2half2_rn(regA[buf][0].x, regA[buf][0].y); \
        __half2 h1 = __floats2half2_rn(regA[buf][0].z, regA[buf][0].w); \
        __half2 h2 = __floats2half2_rn(regA[buf][1].x, regA[buf][1].y); \
        __half2 h3 = __floats2half2_rn(regA[buf][1].z, regA[buf][1].w); \
        uint4 u;                                                \
        u.x = h2_bits(h0); u.y = h2_bits(h1);                   \
        u.z = h2_bits(h2); u.w = h2_bits(h3);                   \
        *(uint4*)(smc + (((c) & 3) * STAGE_B) + aOff) = u;      \
    } while (0)
    #define CPB(c) do {                                                   \
        uint32_t _d = bDst + ((c) & 3) * STAGE_B;                         \
        CP16(_d + bs0 * 16, bSrc + (c) * BK + bs0 * 8);                   \
        CP16(_d + bs1 * 16, bSrc + (c) * BK + bs1 * 8);                   \
        asm volatile("cp.async.commit_group;" ::: "memory");              \
    } while (0)

    float acc[2][8][4];
    #pragma unroll
    for (int i = 0; i < 2; i++)
        #pragma unroll
        for (int t = 0; t < 8; t++)
            #pragma unroll
            for (int q = 0; q < 4; q++) acc[i][t][q] = 0.f;

    LDGA(0, 0); CPB(0);
    LDGA(1, 1); CPB(1);

    #pragma unroll
    for (int c = 0; c < NCH; c++) {
        if (c < NCH - 1) asm volatile("cp.async.wait_group 1;" ::: "memory");
        else             asm volatile("cp.async.wait_group 0;" ::: "memory");
        STSA(c, c & 1);
        __syncthreads();
        if (c + 2 < NCH) { LDGA(c + 2, c & 1); CPB(c + 2); }

        uint32_t stOff = (uint32_t)((c & 3) * STAGE_B);

        #pragma unroll
        for (int ks = 0; ks < 2; ks++) {
            uint32_t ko = stOff + ks * 32u;    // 16 halves = 32 B
            uint32_t a[2][4];
            LDSM4(a[0][0], a[0][1], a[0][2], a[0][3], aLm[0] + ko);
            LDSM4(a[1][0], a[1][1], a[1][2], a[1][3], aLm[1] + ko);
            uint32_t bf[4][4];
            #pragma unroll
            for (int p = 0; p < 4; p++)
                LDSM4(bf[p][0], bf[p][1], bf[p][2], bf[p][3], bLm[p] + ko);
            #pragma unroll
            for (int t = 0; t < 8; t++) {
                uint32_t b0 = bf[t >> 1][(t & 1) * 2 + 0];
                uint32_t b1 = bf[t >> 1][(t & 1) * 2 + 1];
                #pragma unroll
                for (int i = 0; i < 2; i++) mma16(acc[i][t], a[i], b0, b1);
            }
        }
    }
    #undef LDGA
    #undef STSA
    #undef CPB

    // ---- epilogue ----
    #pragma unroll
    for (int i = 0; i < 2; i++) {
        #pragma unroll
        for (int rh = 0; rh < 2; rh++) {
            float s = 0.f;
            #pragma unroll
            for (int t = 0; t < 8; t++) {
                int n0 = wn * 64 + t * 8 + 2 * lt;
                float c0 = acc[i][t][rh * 2 + 0] + rp_s[n0];
                float c1 = acc[i][t][rh * 2 + 1] + rp_s[n0 + 1];
                s += c0 * c0 + c1 * c1;
            }
            s += __shfl_xor_sync(0xffffffffu, s, 1);
            s += __shfl_xor_sync(0xffffffffu, s, 2);
            if (lt == 0) sqp[wm * 32 + i * 16 + rh * 8 + lg][wn] = s;
        }
    }
    __syncthreads();
    if (tid < BM) {
        float sq = sqp[tid][0] + sqp[tid][1] + sqp[tid][2] + sqp[tid][3];
        invb[tid] = 1.0f / fmaxf(sqrtf(sq), 1e-12f);
    }
    __syncthreads();

    #pragma unroll
    for (int i = 0; i < 2; i++) {
        #pragma unroll
        for (int rh = 0; rh < 2; rh++) {
            int row = wm * 32 + i * 16 + rh * 8 + lg;
            float inv = invb[row];
            float s = 0.f;
            #pragma unroll
            for (int t = 0; t < 8; t++) {
                int n0 = wn * 64 + t * 8 + 2 * lt;
                float t0 = (acc[i][t][rh * 2 + 0] + rp_s[n0])     * inv;
                float t1 = (acc[i][t][rh * 2 + 1] + rp_s[n0 + 1]) * inv;
                s += fabsf(hn_s[n0] - t0) + fabsf(hn_s[n0 + 1] - t1);
            }
            s += __shfl_xor_sync(0xffffffffu, s, 1);
            s += __shfl_xor_sync(0xffffffffu, s, 2);
            if (lt == 0) spp[row][wn] = s;
        }
    }
    __syncthreads();
    if (tid < BM)
        out[b * NNEG + tile0 + tid] =
            12.0f - (spp[tid][0] + spp[tid][1] + spp[tid][2] + spp[tid][3]);
}

// ---------------------------------------------------------------------------
extern "C" void kernel_launch(void* const* d_in, const int* in_sizes, int n_in,
                              void* d_out, int out_size)
{
    const int*   head = (const int*)  d_in[0];
    const int*   tail = (const int*)  d_in[1];
    const int*   rel  = (const int*)  d_in[2];
    const float* ent  = (const float*)d_in[3];
    const float* remb = (const float*)d_in[4];
    const float* W    = (const float*)d_in[5];
    const float* bfc  = (const float*)d_in[6];
    float* out = (float*)d_out;

    cudaFuncSetAttribute(k_main, cudaFuncAttributeMaxDynamicSharedMemorySize, SMEM_MAIN);

    k_cvtW<<<DD, 256>>>(W);
    k_prep<<<NB, 256>>>(head, rel, ent, remb, W, bfc);
    k_main<<<dim3(NNEG / BM, NB), 512, SMEM_MAIN>>>(tail, ent, out);
}